// round 17
// baseline (speedup 1.0000x reference)
#include <cuda_runtime.h>
#include <cuda_fp16.h>
#include <cstdint>

// Problem shape (fixed by the reference)
#define Bn 8
#define Tn 1024
#define Cn 768
#define Hn 8
#define Dn 96
#define Mn (Bn*Tn)      // 8192 rows
#define N3 (3*Cn)       // 2304
#define Kd 768

// ---------------------------------------------------------------------------
// Scratch (allocation-free rule: __device__ globals)
// ---------------------------------------------------------------------------
__device__ __half g_x16[(size_t)Mn * Cn];
__device__ __half g_y16[(size_t)Mn * Cn];
__device__ __half g_WaT[(size_t)N3 * Cn];  // W_attn^T [2304,768]
__device__ __half g_WpT[(size_t)Cn * Cn];  // W_proj^T [768,768]
// Attention operands, all [bh][1024][96] row-major fp16
#define AQE ((size_t)Bn * Hn * Tn * Dn)
__device__ __half g_Q16[AQE], g_K16[AQE], g_V16[AQE];

// ---------------------------------------------------------------------------
// Portable tensor-core primitives (sm_80+, legal at .target sm_103)
// ---------------------------------------------------------------------------
__device__ __forceinline__ uint32_t smem_u32(const void* p) {
    uint32_t a;
    asm("{ .reg .u64 t; cvta.to.shared.u64 t, %1; cvt.u32.u64 %0, t; }" : "=r"(a) : "l"(p));
    return a;
}
__device__ __forceinline__ void ldsm_x4(uint32_t* r, uint32_t addr) {
    asm volatile("ldmatrix.sync.aligned.m8n8.x4.shared.b16 {%0,%1,%2,%3}, [%4];"
                 : "=r"(r[0]), "=r"(r[1]), "=r"(r[2]), "=r"(r[3]) : "r"(addr));
}
__device__ __forceinline__ void ldsm_x4_trans(uint32_t* r, uint32_t addr) {
    asm volatile("ldmatrix.sync.aligned.m8n8.x4.trans.shared.b16 {%0,%1,%2,%3}, [%4];"
                 : "=r"(r[0]), "=r"(r[1]), "=r"(r[2]), "=r"(r[3]) : "r"(addr));
}
__device__ __forceinline__ void mma_16816(float* c, const uint32_t* a, const uint32_t* b) {
    asm volatile("mma.sync.aligned.m16n8k16.row.col.f32.f16.f16.f32 "
                 "{%0,%1,%2,%3}, {%4,%5,%6,%7}, {%8,%9}, {%0,%1,%2,%3};"
                 : "+f"(c[0]), "+f"(c[1]), "+f"(c[2]), "+f"(c[3])
                 : "r"(a[0]), "r"(a[1]), "r"(a[2]), "r"(a[3]), "r"(b[0]), "r"(b[1]));
}
__device__ __forceinline__ void cp16(uint32_t saddr, const void* g) {
    asm volatile("cp.async.cg.shared.global [%0], [%1], 16;" :: "r"(saddr), "l"(g));
}
#define CP_COMMIT() asm volatile("cp.async.commit_group;" ::: "memory")
#define CP_WAIT0()  asm volatile("cp.async.wait_group 0;" ::: "memory")
#define CP_WAIT1()  asm volatile("cp.async.wait_group 1;" ::: "memory")

__device__ __forceinline__ uint32_t pack2h(float a, float b) {
    __half2 p = __floats2half2_rn(a, b);
    return *(uint32_t*)&p;
}

// ---------------------------------------------------------------------------
// Fused prep: x -> fp16 | W_attn^T fp16 | W_proj^T fp16, one launch.
// ---------------------------------------------------------------------------
#define PREP_CVT_BLKS  ((Mn * Cn / 4) / 256)          // 6144
#define PREP_WA_BLKS   ((N3 / 32) * (Kd / 32))        // 1728
#define PREP_WP_BLKS   ((Cn / 32) * (Kd / 32))        // 576
#define PREP_BLKS      (PREP_CVT_BLKS + PREP_WA_BLKS + PREP_WP_BLKS)

__device__ __forceinline__ void transpose_tile(const float* __restrict__ W,
                                               __half* __restrict__ T,
                                               int Ndim, int bx, int by, int tid)
{
    __shared__ float t[32][33];
    int tx = tid & 31, ty = tid >> 5;
    int n0 = bx * 32, k0 = by * 32;
#pragma unroll
    for (int i = 0; i < 32; i += 8)
        t[ty + i][tx] = W[(size_t)(k0 + ty + i) * Ndim + n0 + tx];
    __syncthreads();
#pragma unroll
    for (int i = 0; i < 32; i += 8)
        T[(size_t)(n0 + ty + i) * Kd + k0 + tx] = __float2half_rn(t[tx][ty + i]);
}

__global__ __launch_bounds__(256)
void prep_all(const float* __restrict__ x, const float* __restrict__ Wa,
              const float* __restrict__ Wp)
{
    const int blk = blockIdx.x, tid = threadIdx.x;
    if (blk < PREP_CVT_BLKS) {
        int i = blk * 256 + tid;
        float4 v = ((const float4*)x)[i];
        ((uint32_t*)g_x16)[i * 2]     = pack2h(v.x, v.y);
        ((uint32_t*)g_x16)[i * 2 + 1] = pack2h(v.z, v.w);
    } else if (blk < PREP_CVT_BLKS + PREP_WA_BLKS) {
        int b = blk - PREP_CVT_BLKS;
        transpose_tile(Wa, g_WaT, N3, b % (N3 / 32), b / (N3 / 32), tid);
    } else {
        int b = blk - PREP_CVT_BLKS - PREP_WA_BLKS;
        transpose_tile(Wp, g_WpT, Cn, b % (Cn / 32), b / (Cn / 32), tid);
    }
}

// ---------------------------------------------------------------------------
// GEMM geometry shared constants
// ---------------------------------------------------------------------------
#define ROWB 144
#define ATILEB (128 * ROWB)

extern __shared__ float sm_dyn[];

template<int BN>
__device__ __forceinline__ void gemm_issue_stage(
    const __half* A, const __half* B, uint32_t sdst, int kt, int tid)
{
#pragma unroll
    for (int i = 0; i < 4; i++) {                 // A: 128 rows x 8 chunks
        int id = i * 256 + tid;
        int r = id >> 3, c = id & 7;
        cp16(sdst + r * ROWB + c * 16, A + (size_t)r * Kd + kt * 64 + c * 8);
    }
#pragma unroll
    for (int i = 0; i < BN / 32; i++) {           // B: BN rows x 8 chunks
        int id = i * 256 + tid;
        int r = id >> 3, c = id & 7;
        cp16(sdst + ATILEB + r * ROWB + c * 16, B + (size_t)r * Kd + kt * 64 + c * 8);
    }
    CP_COMMIT();
}

// ---------------------------------------------------------------------------
// Fused QKV GEMM (unchanged): BN=256, epilogue writes fp16 directly into
// attention layouts (Q pre-scaled, K, V all [bh][t][96]).
// ---------------------------------------------------------------------------
#define QKV_STAGEB (ATILEB + 256 * ROWB)
#define QKV_SMEM (3 * QKV_STAGEB)     // 165888 B

__global__ __launch_bounds__(256, 1)
void qkv_gemm(const __half* __restrict__ A, const __half* __restrict__ BT,
              const float* __restrict__ bias)
{
    constexpr int NF = 8;
    const int tid = threadIdx.x;
    const int wid = tid >> 5, lane = tid & 31;
    const int m0 = blockIdx.y * 128;
    const int n0 = blockIdx.x * 256;
    const int wm = (wid >> 2) * 64;
    const int wn = (wid & 3) * 64;

    const uint32_t sbase = smem_u32(sm_dyn);
    const __half* Ab_g = A + (size_t)m0 * Kd;
    const __half* Bb_g = BT + (size_t)n0 * Kd;

    float acc[4][NF][4];
#pragma unroll
    for (int mf = 0; mf < 4; mf++)
#pragma unroll
        for (int nf = 0; nf < NF; nf++)
#pragma unroll
            for (int j = 0; j < 4; j++) acc[mf][nf][j] = 0.f;

    const int arow = wm + (lane & 15);
    const int akb  = (lane >> 4) << 3;
    const int brow = wn + (lane & 7) + ((lane >> 4) << 3);
    const int bkb  = ((lane >> 3) & 1) << 3;

    gemm_issue_stage<256>(Ab_g, Bb_g, sbase, 0, tid);
    gemm_issue_stage<256>(Ab_g, Bb_g, sbase + QKV_STAGEB, 1, tid);

    for (int kt = 0; kt < 12; kt++) {
        if (kt < 11) CP_WAIT1(); else CP_WAIT0();
        __syncthreads();

        if (kt + 2 < 12)
            gemm_issue_stage<256>(Ab_g, Bb_g, sbase + ((kt + 2) % 3) * QKV_STAGEB, kt + 2, tid);

        const uint32_t Ab = sbase + (kt % 3) * QKV_STAGEB;
        const uint32_t Bb = Ab + ATILEB;

#pragma unroll
        for (int kf = 0; kf < 4; kf++) {
            const int kb = kf * 16;
            uint32_t a4[4][4], b4[NF][2];
#pragma unroll
            for (int mf = 0; mf < 4; mf++)
                ldsm_x4(a4[mf], Ab + (uint32_t)(arow + mf * 16) * ROWB + (kb + akb) * 2);
#pragma unroll
            for (int np = 0; np < NF / 2; np++) {
                uint32_t t4[4];
                ldsm_x4(t4, Bb + (uint32_t)(brow + np * 16) * ROWB + (kb + bkb) * 2);
                b4[2 * np][0] = t4[0]; b4[2 * np][1] = t4[1];
                b4[2 * np + 1][0] = t4[2]; b4[2 * np + 1][1] = t4[3];
            }
#pragma unroll
            for (int mf = 0; mf < 4; mf++)
#pragma unroll
                for (int nf = 0; nf < NF; nf++)
                    mma_16816(acc[mf][nf], a4[mf], b4[nf]);
        }
    }

    const int sec = n0 / Cn;                          // 0=q, 1=k, 2=v (uniform)
    __half* dst = (sec == 0) ? g_Q16 : (sec == 1) ? g_K16 : g_V16;
    const float scale = (sec == 0) ? rsqrtf((float)Dn) : 1.f;

    const int mrow = m0 + wm + (lane >> 2);
    const int ncol = n0 + wn + (lane & 3) * 2;
#pragma unroll
    for (int mf = 0; mf < 4; mf++)
#pragma unroll
        for (int nf = 0; nf < NF; nf++) {
            int r = mrow + mf * 16;
            int c = ncol + nf * 8;
            int cs = c - sec * Cn;
            int h = cs / Dn, d = cs - h * Dn;
            float b0 = bias[c], b1 = bias[c + 1];
            int b = r >> 10, t = r & 1023;
            size_t off = (((size_t)(b * Hn + h) * Tn + t) * Dn + d);
            *(uint32_t*)(dst + off) =
                pack2h((acc[mf][nf][0] + b0) * scale, (acc[mf][nf][1] + b1) * scale);
            *(uint32_t*)(dst + off + (size_t)8 * Dn) =
                pack2h((acc[mf][nf][2] + b0) * scale, (acc[mf][nf][3] + b1) * scale);
        }
}

// ---------------------------------------------------------------------------
// Projection GEMM: BN=128, 2 CTAs/SM (unchanged from R16).
// ---------------------------------------------------------------------------
#define PROJ_STAGEB (ATILEB + 128 * ROWB)
#define PROJ_SMEM (3 * PROJ_STAGEB)   // 110592 B

__global__ __launch_bounds__(256, 2)
void proj_gemm(const __half* __restrict__ A, const __half* __restrict__ BT,
               const float* __restrict__ bias, float* __restrict__ Cout)
{
    constexpr int NF = 4;
    const int tid = threadIdx.x;
    const int wid = tid >> 5, lane = tid & 31;
    const int m0 = blockIdx.y * 128;
    const int n0 = blockIdx.x * 128;
    const int wm = (wid >> 2) * 64;
    const int wn = (wid & 3) * 32;

    const uint32_t sbase = smem_u32(sm_dyn);
    const __half* Ab_g = A + (size_t)m0 * Kd;
    const __half* Bb_g = BT + (size_t)n0 * Kd;

    float acc[4][NF][4];
#pragma unroll
    for (int mf = 0; mf < 4; mf++)
#pragma unroll
        for (int nf = 0; nf < NF; nf++)
#pragma unroll
            for (int j = 0; j < 4; j++) acc[mf][nf][j] = 0.f;

    const int arow = wm + (lane & 15);
    const int akb  = (lane >> 4) << 3;
    const int brow = wn + (lane & 7) + ((lane >> 4) << 3);
    const int bkb  = ((lane >> 3) & 1) << 3;

    gemm_issue_stage<128>(Ab_g, Bb_g, sbase, 0, tid);
    gemm_issue_stage<128>(Ab_g, Bb_g, sbase + PROJ_STAGEB, 1, tid);

    for (int kt = 0; kt < 12; kt++) {
        if (kt < 11) CP_WAIT1(); else CP_WAIT0();
        __syncthreads();

        if (kt + 2 < 12)
            gemm_issue_stage<128>(Ab_g, Bb_g, sbase + ((kt + 2) % 3) * PROJ_STAGEB, kt + 2, tid);

        const uint32_t Ab = sbase + (kt % 3) * PROJ_STAGEB;
        const uint32_t Bb = Ab + ATILEB;

#pragma unroll
        for (int kf = 0; kf < 4; kf++) {
            const int kb = kf * 16;
            uint32_t a4[4][4], b4[NF][2];
#pragma unroll
            for (int mf = 0; mf < 4; mf++)
                ldsm_x4(a4[mf], Ab + (uint32_t)(arow + mf * 16) * ROWB + (kb + akb) * 2);
#pragma unroll
            for (int np = 0; np < NF / 2; np++) {
                uint32_t t4[4];
                ldsm_x4(t4, Bb + (uint32_t)(brow + np * 16) * ROWB + (kb + bkb) * 2);
                b4[2 * np][0] = t4[0]; b4[2 * np][1] = t4[1];
                b4[2 * np + 1][0] = t4[2]; b4[2 * np + 1][1] = t4[3];
            }
#pragma unroll
            for (int mf = 0; mf < 4; mf++)
#pragma unroll
                for (int nf = 0; nf < NF; nf++)
                    mma_16816(acc[mf][nf], a4[mf], b4[nf]);
        }
    }

    const int mrow = m0 + wm + (lane >> 2);
    const int ncol = n0 + wn + (lane & 3) * 2;
#pragma unroll
    for (int mf = 0; mf < 4; mf++)
#pragma unroll
        for (int nf = 0; nf < NF; nf++) {
            int r = mrow + mf * 16, c = ncol + nf * 8;
            float b0 = bias[c], b1 = bias[c + 1];
            *(float2*)(Cout + (size_t)r * Cn + c) =
                make_float2(acc[mf][nf][0] + b0, acc[mf][nf][1] + b1);
            *(float2*)(Cout + (size_t)(r + 8) * Cn + c) =
                make_float2(acc[mf][nf][2] + b0, acc[mf][nf][3] + b1);
        }
}

// ---------------------------------------------------------------------------
// Tensor-core flash attention, fp16, NOW 2 CTAs/SM:
//  - Q single tile (re-read via ldsm each iter, no reg preload)
//  - K double-buffered, V single-buffered, staggered commits (R12 scheme):
//      wait K(kt) | issue K(kt+1) | S+softmax | wait V(kt) | PV | sync |
//      issue V(kt+1)
//    Co-resident CTA covers the wait bubbles.
// smem: Q + 2xK + V = 4 x 26624 = 106496 B/CTA (x2 = 212992 < 228 KB)
// ---------------------------------------------------------------------------
#define SQp 208
#define TILE_SM (128 * SQp)
#define AOFF_Q 0
#define AOFF_K TILE_SM
#define AOFF_V (AOFF_K + 2 * TILE_SM)
#define ATT_SMEM (AOFF_V + TILE_SM)   // 106496 B

__device__ __forceinline__ void att_load_K(uint32_t kbase, const __half* k, int tid)
{
    for (int i = tid; i < 128 * 12; i += 256) {
        int r = i / 12, c = i - r * 12;
        cp16(kbase + r * SQp + c * 16, k + r * Dn + c * 8);
    }
    CP_COMMIT();
}
__device__ __forceinline__ void att_load_V(uint32_t sb, const __half* v, int tid)
{
    for (int i = tid; i < 128 * 12; i += 256) {
        int r = i / 12, c = i - r * 12;
        cp16(sb + AOFF_V + r * SQp + c * 16, v + r * Dn + c * 8);
    }
    CP_COMMIT();
}

__global__ __launch_bounds__(256, 2)
void attention_mma()
{
    const int tid = threadIdx.x, lane = tid & 31, w = tid >> 5;
    const int qt = gridDim.x - 1 - blockIdx.x;   // long CTAs first
    const int bh = blockIdx.y;
    const int b = bh >> 3, h = bh & 7;
    const uint32_t sb = smem_u32(sm_dyn);

    const __half* gQ = g_Q16 + ((size_t)bh * Tn + qt * 128) * Dn;
    const __half* gK = g_K16 + (size_t)bh * Tn * Dn;
    const __half* gV = g_V16 + (size_t)bh * Tn * Dn;

    // Preamble: Q + K0 as one group, V0 as second group
    for (int i = tid; i < 128 * 12; i += 256) {
        int r = i / 12, c = i - r * 12;
        cp16(sb + AOFF_Q + r * SQp + c * 16, gQ + r * Dn + c * 8);
        cp16(sb + AOFF_K + r * SQp + c * 16, gK + r * Dn + c * 8);
    }
    CP_COMMIT();
    att_load_V(sb, gV, tid);

    float oacc[12][4];
#pragma unroll
    for (int i = 0; i < 12; i++)
#pragma unroll
        for (int j = 0; j < 4; j++) oacc[i][j] = 0.f;
    float m0 = -1e30f, m1 = -1e30f, l0 = 0.f, l1 = 0.f;

    for (int kt = 0; kt <= qt; kt++) {
        // wait Q+K(kt) (V(kt) may still be in flight)
        CP_WAIT1();
        __syncthreads();

        // prefetch K(kt+1) into the other K stage (overlaps S+softmax+PV)
        if (kt < qt)
            att_load_K(sb + AOFF_K + ((kt + 1) & 1) * TILE_SM,
                       gK + (size_t)(kt + 1) * 128 * Dn, tid);

        const uint32_t Kb = sb + AOFF_K + (kt & 1) * TILE_SM;

        // ---- S = Q K^T (Q fragments re-read from smem) ----
        float sacc[16][4];
#pragma unroll
        for (int i = 0; i < 16; i++)
#pragma unroll
            for (int j = 0; j < 4; j++) sacc[i][j] = 0.f;

#pragma unroll
        for (int kf = 0; kf < 6; kf++) {
            uint32_t qa[4];
            ldsm_x4(qa, sb + AOFF_Q +
                    (uint32_t)(w * 16 + (lane & 15)) * SQp + kf * 32 + (lane >> 4) * 16);
#pragma unroll
            for (int p = 0; p < 8; p++) {
                uint32_t k4[4];
                ldsm_x4(k4, Kb + (uint32_t)(p * 16 + (lane & 15)) * SQp + kf * 32 + (lane >> 4) * 16);
                uint32_t b0[2] = {k4[0], k4[2]}, b1[2] = {k4[1], k4[3]};
                mma_16816(sacc[2 * p],     qa, b0);
                mma_16816(sacc[2 * p + 1], qa, b1);
            }
        }

        if (kt == qt) {
            const int lr0 = w * 16 + (lane >> 2), lr1 = lr0 + 8;
#pragma unroll
            for (int nf = 0; nf < 16; nf++) {
                int lc = nf * 8 + (lane & 3) * 2;
                if (lc     > lr0) sacc[nf][0] = -1e30f;
                if (lc + 1 > lr0) sacc[nf][1] = -1e30f;
                if (lc     > lr1) sacc[nf][2] = -1e30f;
                if (lc + 1 > lr1) sacc[nf][3] = -1e30f;
            }
        }

        // ---- online softmax ----
        float tm0 = -1e30f, tm1 = -1e30f;
#pragma unroll
        for (int nf = 0; nf < 16; nf++) {
            tm0 = fmaxf(tm0, fmaxf(sacc[nf][0], sacc[nf][1]));
            tm1 = fmaxf(tm1, fmaxf(sacc[nf][2], sacc[nf][3]));
        }
        tm0 = fmaxf(tm0, __shfl_xor_sync(0xffffffffu, tm0, 1));
        tm0 = fmaxf(tm0, __shfl_xor_sync(0xffffffffu, tm0, 2));
        tm1 = fmaxf(tm1, __shfl_xor_sync(0xffffffffu, tm1, 1));
        tm1 = fmaxf(tm1, __shfl_xor_sync(0xffffffffu, tm1, 2));
        float nm0 = fmaxf(m0, tm0), nm1 = fmaxf(m1, tm1);
        float c0 = __expf(m0 - nm0), c1 = __expf(m1 - nm1);
        m0 = nm0; m1 = nm1;
        float ts0 = 0.f, ts1 = 0.f;
#pragma unroll
        for (int nf = 0; nf < 16; nf++) {
            sacc[nf][0] = __expf(sacc[nf][0] - nm0);
            sacc[nf][1] = __expf(sacc[nf][1] - nm0);
            sacc[nf][2] = __expf(sacc[nf][2] - nm1);
            sacc[nf][3] = __expf(sacc[nf][3] - nm1);
            ts0 += sacc[nf][0] + sacc[nf][1];
            ts1 += sacc[nf][2] + sacc[nf][3];
        }
        ts0 += __shfl_xor_sync(0xffffffffu, ts0, 1);
        ts0 += __shfl_xor_sync(0xffffffffu, ts0, 2);
        ts1 += __shfl_xor_sync(0xffffffffu, ts1, 1);
        ts1 += __shfl_xor_sync(0xffffffffu, ts1, 2);
        l0 = l0 * c0 + ts0;
        l1 = l1 * c1 + ts1;
#pragma unroll
        for (int nf = 0; nf < 12; nf++) {
            oacc[nf][0] *= c0; oacc[nf][1] *= c0;
            oacc[nf][2] *= c1; oacc[nf][3] *= c1;
        }

        // wait V(kt): only K(kt+1) may remain in flight
        if (kt < qt) CP_WAIT1(); else CP_WAIT0();
        __syncthreads();

        // ---- O += P V   (V row-major [t][d], trans-ldmatrix B fragments) ----
        const uint32_t Vb = sb + AOFF_V;
#pragma unroll
        for (int t = 0; t < 8; t++) {
            uint32_t pa[4];
            pa[0] = pack2h(sacc[2 * t][0],     sacc[2 * t][1]);
            pa[1] = pack2h(sacc[2 * t][2],     sacc[2 * t][3]);
            pa[2] = pack2h(sacc[2 * t + 1][0], sacc[2 * t + 1][1]);
            pa[3] = pack2h(sacc[2 * t + 1][2], sacc[2 * t + 1][3]);
#pragma unroll
            for (int dg = 0; dg < 6; dg++) {
                uint32_t v4[4];
                ldsm_x4_trans(v4, Vb + (uint32_t)(t * 16 + (lane & 15)) * SQp
                                     + dg * 32 + (lane >> 4) * 16);
                uint32_t b0[2] = {v4[0], v4[1]}, b1[2] = {v4[2], v4[3]};
                mma_16816(oacc[2 * dg],     pa, b0);
                mma_16816(oacc[2 * dg + 1], pa, b1);
            }
        }

        // all warps done reading V(kt) -> safe to overwrite
        __syncthreads();
        if (kt < qt)
            att_load_V(sb, gV + (size_t)(kt + 1) * 128 * Dn, tid);
    }

    // ---- epilogue: normalize, write y fp16 [B*T, C] ----
    const float i0 = 1.f / l0, i1 = 1.f / l1;
    const size_t row0 = (size_t)b * Tn + qt * 128 + w * 16 + (lane >> 2);
#pragma unroll
    for (int nf = 0; nf < 12; nf++) {
        int col = h * Dn + nf * 8 + (lane & 3) * 2;
        *(uint32_t*)(g_y16 + row0 * Cn + col) =
            pack2h(oacc[nf][0] * i0, oacc[nf][1] * i0);
        *(uint32_t*)(g_y16 + (row0 + 8) * Cn + col) =
            pack2h(oacc[nf][2] * i1, oacc[nf][3] * i1);
    }
}

// ---------------------------------------------------------------------------
// Launch pipeline
// ---------------------------------------------------------------------------
extern "C" void kernel_launch(void* const* d_in, const int* in_sizes, int n_in,
                              void* d_out, int out_size)
{
    const float* x      = (const float*)d_in[0];
    const float* W_attn = (const float*)d_in[1];
    const float* b_attn = (const float*)d_in[2];
    const float* W_proj = (const float*)d_in[3];
    const float* b_proj = (const float*)d_in[4];
    float* out = (float*)d_out;

    __half *x16, *y16, *wat, *wpt;
    cudaGetSymbolAddress((void**)&x16, g_x16);
    cudaGetSymbolAddress((void**)&y16, g_y16);
    cudaGetSymbolAddress((void**)&wat, g_WaT);
    cudaGetSymbolAddress((void**)&wpt, g_WpT);

    cudaFuncSetAttribute(qkv_gemm,
                         cudaFuncAttributeMaxDynamicSharedMemorySize, QKV_SMEM);
    cudaFuncSetAttribute(proj_gemm,
                         cudaFuncAttributeMaxDynamicSharedMemorySize, PROJ_SMEM);
    cudaFuncSetAttribute(attention_mma,
                         cudaFuncAttributeMaxDynamicSharedMemorySize, ATT_SMEM);

    // 0) fused input prep (x convert + both weight transposes, one launch)
    prep_all<<<PREP_BLKS, 256>>>(x, W_attn, W_proj);

    // 1) fused qkv GEMM -> Q16/K16/V16 directly
    qkv_gemm<<<dim3(N3 / 256, Mn / 128), 256, QKV_SMEM>>>(x16, wat, b_attn);

    // 2) pipelined flash attention (tensor cores, 2 CTAs/SM)
    attention_mma<<<dim3(Tn / 128, Bn * Hn), 256, ATT_SMEM>>>();

    // 3) out = y @ W_proj + b_proj   [8192, 768]  (2 CTAs/SM)
    proj_gemm<<<dim3(Cn / 128, Mn / 128), 256, PROJ_SMEM>>>(
        y16, wpt, b_proj, out);
}